// round 7
// baseline (speedup 1.0000x reference)
#include <cuda_runtime.h>
#include <cuda_fp16.h>
#include <cstdint>

#define KMAX   16
#define D_EDGE 128
#define D_SBF  32
#define D_QUAD 32
#define EMAX   100000
#define INV_SQRT_2 0.7071067811865475f

__device__ __align__(16) __half g_st[(size_t)EMAX * D_EDGE];  // silu(x@W_st) fp16
__device__ __align__(16) __half g_ts[(size_t)EMAX * D_EDGE];  // silu(x@W_ts) fp16
__device__ int g_ctr;

__device__ __forceinline__ float silu_f(float z) {
    return __fdividef(z, 1.0f + __expf(-z));
}

// m16n8k16 fp16 MMA, fp32 accumulate
__device__ __forceinline__ void mma4(float* c, const uint32_t* a, uint32_t b0, uint32_t b1) {
    asm volatile(
        "mma.sync.aligned.m16n8k16.row.col.f32.f16.f16.f32 "
        "{%0,%1,%2,%3}, {%4,%5,%6,%7}, {%8,%9}, {%0,%1,%2,%3};\n"
        : "+f"(c[0]), "+f"(c[1]), "+f"(c[2]), "+f"(c[3])
        : "r"(a[0]), "r"(a[1]), "r"(a[2]), "r"(a[3]), "r"(b0), "r"(b1));
}

__device__ __forceinline__ uint32_t h2u(__half2 h) {
    return *reinterpret_cast<uint32_t*>(&h);
}

__global__ void k_zero_ctr() { g_ctr = 0; }

// ===========================================================================
// K_A (fully fused): per 32-edge warp tile (dynamic work distribution):
//   1) S[32,32] = sum_k sbf (HBM stream) -> smem fp16
//   2) m = silu(m_st @ W_down) HMMA (W_down hi/lo split) -> smem fp16
//   3) x = scale * (m (x) S) @ W_bil HMMA (rank-1 A in regs) -> registers
//   4) st = silu(x@W_st), ts = silu(x@W_ts) HMMA, A-frags taken DIRECTLY
//      from phase-3 accumulators (D-layout == A-layout) -> g_st/g_ts fp16
// Persistent: 148 CTAs x 14 warps; all weights resident in smem.
// ===========================================================================
#define KA_WARPS 14
#define KD_PAD   136    // W_down row stride (halfs)
#define HW_PAD   1032   // W_bil row stride (halfs)
#define KU_PAD   40     // W_st/W_ts row stride (halfs)
#define HR_PAD   40     // staged m/S row stride (halfs)
// smem halfs: Wdh(4352)+Wdl(4352)+hW(33024)+Wst(5120)+Wts(5120)+stage(14*2560)
#define OFF_WDL  (32 * KD_PAD)
#define OFF_HW   (2 * 32 * KD_PAD)
#define OFF_WST  (OFF_HW + 32 * HW_PAD)
#define OFF_WTS  (OFF_WST + 128 * KU_PAD)
#define OFF_STG  (OFF_WTS + 128 * KU_PAD)
#define KA_SMEM  ((OFF_STG + KA_WARPS * 2 * 32 * HR_PAD) * 2)

__global__ __launch_bounds__(KA_WARPS * 32, 1)
void k_fused_a(const float* __restrict__ m_st,
               const float* __restrict__ sbf,
               const float* __restrict__ W_down,
               const float* __restrict__ W_bil,
               const float* __restrict__ W_up_st,
               const float* __restrict__ W_up_ts,
               const float* __restrict__ scale_sbf,
               int E) {
    extern __shared__ __half sma[];
    __half* Wdh = sma;
    __half* Wdl = sma + OFF_WDL;
    __half* hW  = sma + OFF_HW;
    __half* Wst = sma + OFF_WST;
    __half* Wts = sma + OFF_WTS;
    const int tid = threadIdx.x;
    const int wid = tid >> 5;
    const int lane = tid & 31;
    __half* hm = sma + OFF_STG + wid * (2 * 32 * HR_PAD);
    __half* hS = hm + 32 * HR_PAD;

    // --- resident weights ---
    for (int idx = tid; idx < 128 * 32; idx += KA_WARPS * 32) {
        int k = idx >> 5, o = idx & 31;
        float w = W_down[idx];
        __half h = __float2half_rn(w);
        Wdh[o * KD_PAD + k] = h;
        Wdl[o * KD_PAD + k] = __float2half_rn(w - __half2float(h));
    }
    for (int idx = tid; idx < 1024 * 32; idx += KA_WARPS * 32) {
        int k = idx >> 5, o = idx & 31;
        hW[o * HW_PAD + k] = __float2half_rn(W_bil[idx]);
    }
    for (int idx = tid; idx < 32 * 128; idx += KA_WARPS * 32) {
        int q = idx >> 7, o = idx & 127;
        Wst[o * KU_PAD + q] = __float2half_rn(W_up_st[idx]);
        Wts[o * KU_PAD + q] = __float2half_rn(W_up_ts[idx]);
    }
    __syncthreads();

    const float sc = scale_sbf[0];
    const int r0 = lane >> 2, qt = lane & 3;
    const int ngroups = (E + 31) >> 5;

    for (;;) {
        int g;
        if (lane == 0) g = atomicAdd(&g_ctr, 1);
        g = __shfl_sync(0xffffffffu, g, 0);
        if (g >= ngroups) break;
        const int e0 = g * 32;

        // ---- phase 1: S-reduce (205MB HBM stream) ----
#pragma unroll
        for (int h2i = 0; h2i < 2; h2i++) {
            const int r = h2i * 16 + (lane >> 1);
            const int p = lane & 1;
            const int e = min(e0 + r, E - 1);
            const float4* sp = reinterpret_cast<const float4*>(sbf + (size_t)e * 512) + p * 4;
            float4 a0 = make_float4(0.f, 0.f, 0.f, 0.f);
            float4 a1 = a0, a2 = a0, a3 = a0;
#pragma unroll 4
            for (int k = 0; k < KMAX; k++) {
                float4 v0 = sp[k * 8 + 0];
                float4 v1 = sp[k * 8 + 1];
                float4 v2 = sp[k * 8 + 2];
                float4 v3 = sp[k * 8 + 3];
                a0.x += v0.x; a0.y += v0.y; a0.z += v0.z; a0.w += v0.w;
                a1.x += v1.x; a1.y += v1.y; a1.z += v1.z; a1.w += v1.w;
                a2.x += v2.x; a2.y += v2.y; a2.z += v2.z; a2.w += v2.w;
                a3.x += v3.x; a3.y += v3.y; a3.z += v3.z; a3.w += v3.w;
            }
            __half2* dst = reinterpret_cast<__half2*>(hS + r * HR_PAD + p * 16);
            dst[0] = __floats2half2_rn(a0.x, a0.y);
            dst[1] = __floats2half2_rn(a0.z, a0.w);
            dst[2] = __floats2half2_rn(a1.x, a1.y);
            dst[3] = __floats2half2_rn(a1.z, a1.w);
            dst[4] = __floats2half2_rn(a2.x, a2.y);
            dst[5] = __floats2half2_rn(a2.z, a2.w);
            dst[6] = __floats2half2_rn(a3.x, a3.y);
            dst[7] = __floats2half2_rn(a3.z, a3.w);
        }

        // ---- phase 2: down-proj HMMA ----
        {
            int ec[2][2];
            ec[0][0] = min(e0 + r0, E - 1);
            ec[0][1] = min(e0 + r0 + 8, E - 1);
            ec[1][0] = min(e0 + 16 + r0, E - 1);
            ec[1][1] = min(e0 + 16 + r0 + 8, E - 1);
            float dacc[2][4][4];
#pragma unroll
            for (int t = 0; t < 2; t++)
#pragma unroll
                for (int nt = 0; nt < 4; nt++)
#pragma unroll
                    for (int j = 0; j < 4; j++) dacc[t][nt][j] = 0.f;

#pragma unroll
            for (int ks = 0; ks < 8; ks++) {
                const int c0 = ks * 16 + qt * 2;
                uint32_t a[2][4];
#pragma unroll
                for (int t = 0; t < 2; t++) {
                    float2 v0 = *reinterpret_cast<const float2*>(m_st + (size_t)ec[t][0] * 128 + c0);
                    float2 v1 = *reinterpret_cast<const float2*>(m_st + (size_t)ec[t][1] * 128 + c0);
                    float2 v2 = *reinterpret_cast<const float2*>(m_st + (size_t)ec[t][0] * 128 + c0 + 8);
                    float2 v3 = *reinterpret_cast<const float2*>(m_st + (size_t)ec[t][1] * 128 + c0 + 8);
                    a[t][0] = h2u(__floats2half2_rn(v0.x, v0.y));
                    a[t][1] = h2u(__floats2half2_rn(v1.x, v1.y));
                    a[t][2] = h2u(__floats2half2_rn(v2.x, v2.y));
                    a[t][3] = h2u(__floats2half2_rn(v3.x, v3.y));
                }
#pragma unroll
                for (int nt = 0; nt < 4; nt++) {
                    const int koff = (nt * 8 + r0) * KD_PAD + c0;
                    uint32_t bh0 = *reinterpret_cast<const uint32_t*>(Wdh + koff);
                    uint32_t bh1 = *reinterpret_cast<const uint32_t*>(Wdh + koff + 8);
                    uint32_t bl0 = *reinterpret_cast<const uint32_t*>(Wdl + koff);
                    uint32_t bl1 = *reinterpret_cast<const uint32_t*>(Wdl + koff + 8);
                    mma4(dacc[0][nt], a[0], bh0, bh1);
                    mma4(dacc[0][nt], a[0], bl0, bl1);
                    mma4(dacc[1][nt], a[1], bh0, bh1);
                    mma4(dacc[1][nt], a[1], bl0, bl1);
                }
            }
#pragma unroll
            for (int t = 0; t < 2; t++)
#pragma unroll
                for (int nt = 0; nt < 4; nt++) {
                    const int col = nt * 8 + qt * 2;
                    *reinterpret_cast<__half2*>(hm + (t * 16 + r0) * HR_PAD + col) =
                        __floats2half2_rn(silu_f(dacc[t][nt][0]), silu_f(dacc[t][nt][1]));
                    *reinterpret_cast<__half2*>(hm + (t * 16 + r0 + 8) * HR_PAD + col) =
                        __floats2half2_rn(silu_f(dacc[t][nt][2]), silu_f(dacc[t][nt][3]));
                }
        }
        __syncwarp();

        // ---- phase 3: bilinear HMMA (x stays in registers) ----
        float acc[2][4][4];
#pragma unroll
        for (int t = 0; t < 2; t++)
#pragma unroll
            for (int nt = 0; nt < 4; nt++)
#pragma unroll
                for (int j = 0; j < 4; j++) acc[t][nt][j] = 0.f;

#pragma unroll 2
        for (int kt = 0; kt < 64; kt++) {
            const int q = kt >> 1;
            const int c0 = (kt & 1) * 16 + qt * 2;

            uint32_t a[2][4];
#pragma unroll
            for (int t = 0; t < 2; t++) {
                const int rb = t * 16;
                __half2 mm0 = __half2half2(hm[(rb + r0) * HR_PAD + q]);
                __half2 mm1 = __half2half2(hm[(rb + r0 + 8) * HR_PAD + q]);
                __half2 s00 = *reinterpret_cast<const __half2*>(&hS[(rb + r0) * HR_PAD + c0]);
                __half2 s01 = *reinterpret_cast<const __half2*>(&hS[(rb + r0) * HR_PAD + c0 + 8]);
                __half2 s10 = *reinterpret_cast<const __half2*>(&hS[(rb + r0 + 8) * HR_PAD + c0]);
                __half2 s11 = *reinterpret_cast<const __half2*>(&hS[(rb + r0 + 8) * HR_PAD + c0 + 8]);
                a[t][0] = h2u(__hmul2(mm0, s00));
                a[t][1] = h2u(__hmul2(mm1, s10));
                a[t][2] = h2u(__hmul2(mm0, s01));
                a[t][3] = h2u(__hmul2(mm1, s11));
            }

            const int kk = kt * 16 + qt * 2;
#pragma unroll
            for (int nt = 0; nt < 4; nt++) {
                const int o = nt * 8 + r0;
                uint32_t b0 = *reinterpret_cast<const uint32_t*>(&hW[o * HW_PAD + kk]);
                uint32_t b1 = *reinterpret_cast<const uint32_t*>(&hW[o * HW_PAD + kk + 8]);
                mma4(acc[0][nt], a[0], b0, b1);
                mma4(acc[1][nt], a[1], b0, b1);
            }
        }

        // ---- phase 4: up-projections; A-frags directly from accumulators ----
        // D-layout of phase 3 == A-layout for m16n8k16:
        //   a[ks][0]=(r0, k=16ks+2qt) = acc[2ks][0..1]
        //   a[ks][1]=(r0+8, same)     = acc[2ks][2..3]
        //   a[ks][2]=(r0, k+8)        = acc[2ks+1][0..1]
        //   a[ks][3]=(r0+8, k+8)      = acc[2ks+1][2..3]
        uint32_t ha[2][2][4];
#pragma unroll
        for (int t = 0; t < 2; t++)
#pragma unroll
            for (int ks = 0; ks < 2; ks++) {
                ha[t][ks][0] = h2u(__floats2half2_rn(acc[t][2 * ks][0] * sc, acc[t][2 * ks][1] * sc));
                ha[t][ks][1] = h2u(__floats2half2_rn(acc[t][2 * ks][2] * sc, acc[t][2 * ks][3] * sc));
                ha[t][ks][2] = h2u(__floats2half2_rn(acc[t][2 * ks + 1][0] * sc, acc[t][2 * ks + 1][1] * sc));
                ha[t][ks][3] = h2u(__floats2half2_rn(acc[t][2 * ks + 1][2] * sc, acc[t][2 * ks + 1][3] * sc));
            }

#pragma unroll 2
        for (int nt = 0; nt < 16; nt++) {
            const int ob = (nt * 8 + r0) * KU_PAD + qt * 2;
            uint32_t bs[2][2], bt[2][2];
#pragma unroll
            for (int ks = 0; ks < 2; ks++) {
                bs[ks][0] = *reinterpret_cast<const uint32_t*>(Wst + ob + ks * 16);
                bs[ks][1] = *reinterpret_cast<const uint32_t*>(Wst + ob + ks * 16 + 8);
                bt[ks][0] = *reinterpret_cast<const uint32_t*>(Wts + ob + ks * 16);
                bt[ks][1] = *reinterpret_cast<const uint32_t*>(Wts + ob + ks * 16 + 8);
            }
#pragma unroll
            for (int t = 0; t < 2; t++) {
                float cs[4] = {0.f, 0.f, 0.f, 0.f};
                float ct[4] = {0.f, 0.f, 0.f, 0.f};
#pragma unroll
                for (int ks = 0; ks < 2; ks++) {
                    mma4(cs, ha[t][ks], bs[ks][0], bs[ks][1]);
                    mma4(ct, ha[t][ks], bt[ks][0], bt[ks][1]);
                }
                const int er0 = e0 + t * 16 + r0;
                const int er1 = er0 + 8;
                const int col = nt * 8 + qt * 2;
                if (er0 < E) {
                    *reinterpret_cast<__half2*>(g_st + (size_t)er0 * 128 + col) =
                        __floats2half2_rn(silu_f(cs[0]), silu_f(cs[1]));
                    *reinterpret_cast<__half2*>(g_ts + (size_t)er0 * 128 + col) =
                        __floats2half2_rn(silu_f(ct[0]), silu_f(ct[1]));
                }
                if (er1 < E) {
                    *reinterpret_cast<__half2*>(g_st + (size_t)er1 * 128 + col) =
                        __floats2half2_rn(silu_f(cs[2]), silu_f(cs[3]));
                    *reinterpret_cast<__half2*>(g_ts + (size_t)er1 * 128 + col) =
                        __floats2half2_rn(silu_f(ct[2]), silu_f(ct[3]));
                }
            }
        }
        __syncwarp();
    }
}

// ===========================================================================
// K_C: out[e] = (st[e] + ts[swap[e]]) * inv_sqrt2  — pure bandwidth (~103MB)
// One warp per edge row; lane handles 4 channels.
// ===========================================================================
__global__ __launch_bounds__(256)
void k_comb(const void* __restrict__ idx_swap,
            float* __restrict__ out,
            int E) {
    bool is64 = true;
    {
        const long long* p = reinterpret_cast<const long long*>(idx_swap);
#pragma unroll
        for (int i = 0; i < 4; i++) {
            long long v = p[i];
            if (v < 0 || v >= (long long)E) is64 = false;
        }
    }
    const int w = (blockIdx.x * blockDim.x + threadIdx.x) >> 5;
    const int lane = threadIdx.x & 31;
    const int nw = (gridDim.x * blockDim.x) >> 5;

    for (int e = w; e < E; e += nw) {
        long long se = is64 ? reinterpret_cast<const long long*>(idx_swap)[e]
                            : (long long)reinterpret_cast<const int*>(idx_swap)[e];
        const int c = lane * 4;
        uint2 su = *reinterpret_cast<const uint2*>(g_st + (size_t)e * 128 + c);
        uint2 tu = *reinterpret_cast<const uint2*>(g_ts + (size_t)se * 128 + c);
        __half2 s0 = *reinterpret_cast<__half2*>(&su.x);
        __half2 s1 = *reinterpret_cast<__half2*>(&su.y);
        __half2 t0 = *reinterpret_cast<__half2*>(&tu.x);
        __half2 t1 = *reinterpret_cast<__half2*>(&tu.y);
        float4 o;
        o.x = (__low2float(s0)  + __low2float(t0))  * INV_SQRT_2;
        o.y = (__high2float(s0) + __high2float(t0)) * INV_SQRT_2;
        o.z = (__low2float(s1)  + __low2float(t1))  * INV_SQRT_2;
        o.w = (__high2float(s1) + __high2float(t1)) * INV_SQRT_2;
        *reinterpret_cast<float4*>(out + (size_t)e * 128 + c) = o;
    }
}

// ===========================================================================
// Launch
// ===========================================================================
extern "C" void kernel_launch(void* const* d_in, const int* in_sizes, int n_in,
                              void* d_out, int out_size) {
    const float* m_st   = (const float*)d_in[0];
    const float* sbf    = (const float*)d_in[1];
    const void*  idxsw  = d_in[2];
    const float* W_down = (const float*)d_in[5];
    const float* W_bil  = (const float*)d_in[6];
    const float* W_st   = (const float*)d_in[7];
    const float* W_ts   = (const float*)d_in[8];
    const float* scale  = (const float*)d_in[9];
    float* out = (float*)d_out;

    const int E = in_sizes[0] / D_EDGE;

    k_zero_ctr<<<1, 1>>>();

    cudaFuncSetAttribute(k_fused_a, cudaFuncAttributeMaxDynamicSharedMemorySize, KA_SMEM);
    k_fused_a<<<148, KA_WARPS * 32, KA_SMEM>>>(m_st, sbf, W_down, W_bil,
                                               W_st, W_ts, scale, E);

    k_comb<<<1536, 256>>>(idxsw, out, E);
}

// round 8
// speedup vs baseline: 1.1331x; 1.1331x over previous
#include <cuda_runtime.h>
#include <cuda_fp16.h>
#include <cstdint>

#define KMAX   16
#define D_EDGE 128
#define D_SBF  32
#define D_QUAD 32
#define EMAX   100000
#define INV_SQRT_2 0.7071067811865475f

__device__ __align__(16) __half g_x_h[(size_t)EMAX * D_QUAD];  // bilinear out (fp16)
__device__ int g_ctr = 0;

__device__ __forceinline__ float silu_f(float z) {
    return __fdividef(z, 1.0f + __expf(-z));
}

// m16n8k16 fp16 MMA, fp32 accumulate
__device__ __forceinline__ void mma4(float* c, const uint32_t* a, uint32_t b0, uint32_t b1) {
    asm volatile(
        "mma.sync.aligned.m16n8k16.row.col.f32.f16.f16.f32 "
        "{%0,%1,%2,%3}, {%4,%5,%6,%7}, {%8,%9}, {%0,%1,%2,%3};\n"
        : "+f"(c[0]), "+f"(c[1]), "+f"(c[2]), "+f"(c[3])
        : "r"(a[0]), "r"(a[1]), "r"(a[2]), "r"(a[3]), "r"(b0), "r"(b1));
}

__device__ __forceinline__ uint32_t h2u(__half2 h) {
    return *reinterpret_cast<uint32_t*>(&h);
}

// ===========================================================================
// K_A (fused, M=32 per warp, dynamic scheduling): per 32-edge warp tile:
//   1) S[32,32] = sum_k sbf — COALESCED row-major stream (4 ideal LDG.128 per
//      row) + shfl_xor butterfly reduce over k-groups -> smem fp16
//   2) m = silu(m_st @ W_down) HMMA (W_down hi/lo split) -> smem fp16
//   3) x = scale * (m (x) S) @ W_bil HMMA (rank-1 A in regs) -> g_x_h fp16
// Persistent: 148 CTAs x 16 warps; weights resident in smem.
// ===========================================================================
#define KA_WARPS 16
#define KD_PAD   136    // W_down row stride (halfs)
#define HW_PAD   1032   // W_bil row stride (halfs)
#define HR_PAD   40     // staged m/S row stride (halfs)
#define OFF_HW   (2 * 32 * KD_PAD)
#define OFF_STG  (OFF_HW + 32 * HW_PAD)
#define KA_SMEM  ((OFF_STG + KA_WARPS * 2 * 32 * HR_PAD) * 2)

__global__ __launch_bounds__(KA_WARPS * 32, 1)
void k_fused_a(const float* __restrict__ m_st,
               const float* __restrict__ sbf,
               const float* __restrict__ W_down,
               const float* __restrict__ W_bil,
               const float* __restrict__ scale_sbf,
               int E) {
    extern __shared__ __half sma[];
    __half* Wdh = sma;                     // [32][KD_PAD]
    __half* Wdl = sma + 32 * KD_PAD;
    __half* hW  = sma + OFF_HW;            // [32][HW_PAD]
    const int tid = threadIdx.x;
    const int wid = tid >> 5;
    const int lane = tid & 31;
    __half* hm = sma + OFF_STG + wid * (2 * 32 * HR_PAD);
    __half* hS = hm + 32 * HR_PAD;

    // --- resident weights ---
    for (int idx = tid; idx < 128 * 32; idx += KA_WARPS * 32) {
        int k = idx >> 5, o = idx & 31;
        float w = W_down[idx];
        __half h = __float2half_rn(w);
        Wdh[o * KD_PAD + k] = h;
        Wdl[o * KD_PAD + k] = __float2half_rn(w - __half2float(h));
    }
    for (int idx = tid; idx < 1024 * 32; idx += KA_WARPS * 32) {
        int k = idx >> 5, o = idx & 31;
        hW[o * HW_PAD + k] = __float2half_rn(W_bil[idx]);
    }
    __syncthreads();

    const float sc = scale_sbf[0];
    const int r0 = lane >> 2, qt = lane & 3;
    const int ngroups = (E + 31) >> 5;

    for (;;) {
        int g;
        if (lane == 0) g = atomicAdd(&g_ctr, 1);
        g = __shfl_sync(0xffffffffu, g, 0);
        if (g >= ngroups) break;
        const int e0 = g * 32;

        // ---- phase 1: coalesced S-reduce ----
        // lane reads float4 #(i*32+lane) of the 2KB row: covers s-slice
        // 4*(lane&7), k-group (lane>>3)+4i. Butterfly over lanes ^8,^16 sums
        // the 4 k-groups; lanes 0..7 hold the row's 32 S values.
        {
            const int sl = 4 * (lane & 7);
#pragma unroll 1
            for (int rr = 0; rr < 32; rr += 2) {
                const int ea = min(e0 + rr, E - 1);
                const int eb = min(e0 + rr + 1, E - 1);
                const float4* ra = reinterpret_cast<const float4*>(sbf + (size_t)ea * 512) + lane;
                const float4* rb = reinterpret_cast<const float4*>(sbf + (size_t)eb * 512) + lane;
                float4 a0 = ra[0], a1 = ra[32], a2 = ra[64], a3 = ra[96];
                float4 b0 = rb[0], b1 = rb[32], b2 = rb[64], b3 = rb[96];
                float4 A, B;
                A.x = (a0.x + a1.x) + (a2.x + a3.x);
                A.y = (a0.y + a1.y) + (a2.y + a3.y);
                A.z = (a0.z + a1.z) + (a2.z + a3.z);
                A.w = (a0.w + a1.w) + (a2.w + a3.w);
                B.x = (b0.x + b1.x) + (b2.x + b3.x);
                B.y = (b0.y + b1.y) + (b2.y + b3.y);
                B.z = (b0.z + b1.z) + (b2.z + b3.z);
                B.w = (b0.w + b1.w) + (b2.w + b3.w);
#pragma unroll
                for (int off = 8; off <= 16; off <<= 1) {
                    A.x += __shfl_xor_sync(0xffffffffu, A.x, off);
                    A.y += __shfl_xor_sync(0xffffffffu, A.y, off);
                    A.z += __shfl_xor_sync(0xffffffffu, A.z, off);
                    A.w += __shfl_xor_sync(0xffffffffu, A.w, off);
                    B.x += __shfl_xor_sync(0xffffffffu, B.x, off);
                    B.y += __shfl_xor_sync(0xffffffffu, B.y, off);
                    B.z += __shfl_xor_sync(0xffffffffu, B.z, off);
                    B.w += __shfl_xor_sync(0xffffffffu, B.w, off);
                }
                if (lane < 8) {
                    uint2 ua, ub;
                    ua.x = h2u(__floats2half2_rn(A.x, A.y));
                    ua.y = h2u(__floats2half2_rn(A.z, A.w));
                    ub.x = h2u(__floats2half2_rn(B.x, B.y));
                    ub.y = h2u(__floats2half2_rn(B.z, B.w));
                    *reinterpret_cast<uint2*>(hS + rr * HR_PAD + sl) = ua;
                    *reinterpret_cast<uint2*>(hS + (rr + 1) * HR_PAD + sl) = ub;
                }
            }
        }
        __syncwarp();

        // ---- phase 2: down-proj HMMA ----
        {
            int ec[2][2];
            ec[0][0] = min(e0 + r0, E - 1);
            ec[0][1] = min(e0 + r0 + 8, E - 1);
            ec[1][0] = min(e0 + 16 + r0, E - 1);
            ec[1][1] = min(e0 + 16 + r0 + 8, E - 1);
            float dacc[2][4][4];
#pragma unroll
            for (int t = 0; t < 2; t++)
#pragma unroll
                for (int nt = 0; nt < 4; nt++)
#pragma unroll
                    for (int j = 0; j < 4; j++) dacc[t][nt][j] = 0.f;

#pragma unroll
            for (int ks = 0; ks < 8; ks++) {
                const int c0 = ks * 16 + qt * 2;
                uint32_t a[2][4];
#pragma unroll
                for (int t = 0; t < 2; t++) {
                    float2 v0 = *reinterpret_cast<const float2*>(m_st + (size_t)ec[t][0] * 128 + c0);
                    float2 v1 = *reinterpret_cast<const float2*>(m_st + (size_t)ec[t][1] * 128 + c0);
                    float2 v2 = *reinterpret_cast<const float2*>(m_st + (size_t)ec[t][0] * 128 + c0 + 8);
                    float2 v3 = *reinterpret_cast<const float2*>(m_st + (size_t)ec[t][1] * 128 + c0 + 8);
                    a[t][0] = h2u(__floats2half2_rn(v0.x, v0.y));
                    a[t][1] = h2u(__floats2half2_rn(v1.x, v1.y));
                    a[t][2] = h2u(__floats2half2_rn(v2.x, v2.y));
                    a[t][3] = h2u(__floats2half2_rn(v3.x, v3.y));
                }
#pragma unroll
                for (int nt = 0; nt < 4; nt++) {
                    const int koff = (nt * 8 + r0) * KD_PAD + c0;
                    uint32_t bh0 = *reinterpret_cast<const uint32_t*>(Wdh + koff);
                    uint32_t bh1 = *reinterpret_cast<const uint32_t*>(Wdh + koff + 8);
                    uint32_t bl0 = *reinterpret_cast<const uint32_t*>(Wdl + koff);
                    uint32_t bl1 = *reinterpret_cast<const uint32_t*>(Wdl + koff + 8);
                    mma4(dacc[0][nt], a[0], bh0, bh1);
                    mma4(dacc[0][nt], a[0], bl0, bl1);
                    mma4(dacc[1][nt], a[1], bh0, bh1);
                    mma4(dacc[1][nt], a[1], bl0, bl1);
                }
            }
#pragma unroll
            for (int t = 0; t < 2; t++)
#pragma unroll
                for (int nt = 0; nt < 4; nt++) {
                    const int col = nt * 8 + qt * 2;
                    *reinterpret_cast<__half2*>(hm + (t * 16 + r0) * HR_PAD + col) =
                        __floats2half2_rn(silu_f(dacc[t][nt][0]), silu_f(dacc[t][nt][1]));
                    *reinterpret_cast<__half2*>(hm + (t * 16 + r0 + 8) * HR_PAD + col) =
                        __floats2half2_rn(silu_f(dacc[t][nt][2]), silu_f(dacc[t][nt][3]));
                }
        }
        __syncwarp();

        // ---- phase 3: bilinear HMMA ----
        float acc[2][4][4];
#pragma unroll
        for (int t = 0; t < 2; t++)
#pragma unroll
            for (int nt = 0; nt < 4; nt++)
#pragma unroll
                for (int j = 0; j < 4; j++) acc[t][nt][j] = 0.f;

#pragma unroll 2
        for (int kt = 0; kt < 64; kt++) {
            const int q = kt >> 1;
            const int c0 = (kt & 1) * 16 + qt * 2;

            uint32_t a[2][4];
#pragma unroll
            for (int t = 0; t < 2; t++) {
                const int rb = t * 16;
                __half2 mm0 = __half2half2(hm[(rb + r0) * HR_PAD + q]);
                __half2 mm1 = __half2half2(hm[(rb + r0 + 8) * HR_PAD + q]);
                __half2 s00 = *reinterpret_cast<const __half2*>(&hS[(rb + r0) * HR_PAD + c0]);
                __half2 s01 = *reinterpret_cast<const __half2*>(&hS[(rb + r0) * HR_PAD + c0 + 8]);
                __half2 s10 = *reinterpret_cast<const __half2*>(&hS[(rb + r0 + 8) * HR_PAD + c0]);
                __half2 s11 = *reinterpret_cast<const __half2*>(&hS[(rb + r0 + 8) * HR_PAD + c0 + 8]);
                a[t][0] = h2u(__hmul2(mm0, s00));
                a[t][1] = h2u(__hmul2(mm1, s10));
                a[t][2] = h2u(__hmul2(mm0, s01));
                a[t][3] = h2u(__hmul2(mm1, s11));
            }

            const int kk = kt * 16 + qt * 2;
#pragma unroll
            for (int nt = 0; nt < 4; nt++) {
                const int o = nt * 8 + r0;
                uint32_t b0 = *reinterpret_cast<const uint32_t*>(&hW[o * HW_PAD + kk]);
                uint32_t b1 = *reinterpret_cast<const uint32_t*>(&hW[o * HW_PAD + kk + 8]);
                mma4(acc[0][nt], a[0], b0, b1);
                mma4(acc[1][nt], a[1], b0, b1);
            }
        }

#pragma unroll
        for (int t = 0; t < 2; t++) {
            const int er0 = e0 + t * 16 + r0;
            const int er1 = er0 + 8;
#pragma unroll
            for (int nt = 0; nt < 4; nt++) {
                const int col = nt * 8 + qt * 2;
                if (er0 < E)
                    *reinterpret_cast<__half2*>(g_x_h + (size_t)er0 * 32 + col) =
                        __floats2half2_rn(acc[t][nt][0] * sc, acc[t][nt][1] * sc);
                if (er1 < E)
                    *reinterpret_cast<__half2*>(g_x_h + (size_t)er1 * 32 + col) =
                        __floats2half2_rn(acc[t][nt][2] * sc, acc[t][nt][3] * sc);
            }
        }
        __syncwarp();
    }
}

// ===========================================================================
// K_B: out = (silu(x@W_st) + silu(x[swap]@W_ts)) * inv_sqrt2 via HMMA.
// Plain fp16 weights in smem; A-frags direct from g_x_h (L2-resident).
// Also resets the dynamic-scheduler counter for the next graph replay.
// ===========================================================================
#define KU_WARPS 8
#define KU_PAD   40
#define KU_W_HALFS (128 * KU_PAD)

__global__ __launch_bounds__(KU_WARPS * 32, 4)
void k_up_mma(const void* __restrict__ idx_swap,
              const float* __restrict__ W_st,
              const float* __restrict__ W_ts,
              float* __restrict__ out,
              int E) {
    if (blockIdx.x == 0 && threadIdx.x == 0) g_ctr = 0;  // reset for next replay

    __shared__ __half Wst[KU_W_HALFS];
    __shared__ __half Wts[KU_W_HALFS];
    const int tid = threadIdx.x;
    const int wid = tid >> 5;
    const int lane = tid & 31;

    for (int idx = tid; idx < 32 * 128; idx += KU_WARPS * 32) {
        int q = idx >> 7, o = idx & 127;
        Wst[o * KU_PAD + q] = __float2half_rn(W_st[idx]);
        Wts[o * KU_PAD + q] = __float2half_rn(W_ts[idx]);
    }
    bool is64 = true;
    {
        const long long* p = reinterpret_cast<const long long*>(idx_swap);
#pragma unroll
        for (int i = 0; i < 4; i++) {
            long long v = p[i];
            if (v < 0 || v >= (long long)E) is64 = false;
        }
    }
    __syncthreads();

    const int r0 = lane >> 2, qt = lane & 3;
    const int ngroups = (E + 15) >> 4;

    for (int g = blockIdx.x * KU_WARPS + wid; g < ngroups; g += gridDim.x * KU_WARPS) {
        const int e0 = g * 16;
        const int er0 = e0 + r0, er1 = er0 + 8;
        const int ec0 = min(er0, E - 1);
        const int ec1 = min(er1, E - 1);
        long long se0, se1;
        if (is64) {
            se0 = reinterpret_cast<const long long*>(idx_swap)[ec0];
            se1 = reinterpret_cast<const long long*>(idx_swap)[ec1];
        } else {
            se0 = reinterpret_cast<const int*>(idx_swap)[ec0];
            se1 = reinterpret_cast<const int*>(idx_swap)[ec1];
        }

        uint32_t aA[2][4], aB[2][4];
#pragma unroll
        for (int ks = 0; ks < 2; ks++) {
            const int ab = ks * 16 + qt * 2;
            aA[ks][0] = *reinterpret_cast<const uint32_t*>(g_x_h + (size_t)ec0 * 32 + ab);
            aA[ks][1] = *reinterpret_cast<const uint32_t*>(g_x_h + (size_t)ec1 * 32 + ab);
            aA[ks][2] = *reinterpret_cast<const uint32_t*>(g_x_h + (size_t)ec0 * 32 + ab + 8);
            aA[ks][3] = *reinterpret_cast<const uint32_t*>(g_x_h + (size_t)ec1 * 32 + ab + 8);
            aB[ks][0] = *reinterpret_cast<const uint32_t*>(g_x_h + (size_t)se0 * 32 + ab);
            aB[ks][1] = *reinterpret_cast<const uint32_t*>(g_x_h + (size_t)se1 * 32 + ab);
            aB[ks][2] = *reinterpret_cast<const uint32_t*>(g_x_h + (size_t)se0 * 32 + ab + 8);
            aB[ks][3] = *reinterpret_cast<const uint32_t*>(g_x_h + (size_t)se1 * 32 + ab + 8);
        }

#pragma unroll 4
        for (int nt = 0; nt < 16; nt++) {
            float cs[4] = {0.f, 0.f, 0.f, 0.f};
            float ct[4] = {0.f, 0.f, 0.f, 0.f};
            const int obase = (nt * 8 + r0) * KU_PAD + qt * 2;
#pragma unroll
            for (int ks = 0; ks < 2; ks++) {
                const int koff = obase + ks * 16;
                uint32_t bs0 = *reinterpret_cast<const uint32_t*>(Wst + koff);
                uint32_t bs1 = *reinterpret_cast<const uint32_t*>(Wst + koff + 8);
                uint32_t bt0 = *reinterpret_cast<const uint32_t*>(Wts + koff);
                uint32_t bt1 = *reinterpret_cast<const uint32_t*>(Wts + koff + 8);
                mma4(cs, aA[ks], bs0, bs1);
                mma4(ct, aB[ks], bt0, bt1);
            }
            const int col = nt * 8 + qt * 2;
            if (er0 < E) {
                float2 o2;
                o2.x = (silu_f(cs[0]) + silu_f(ct[0])) * INV_SQRT_2;
                o2.y = (silu_f(cs[1]) + silu_f(ct[1])) * INV_SQRT_2;
                *reinterpret_cast<float2*>(out + (size_t)er0 * 128 + col) = o2;
            }
            if (er1 < E) {
                float2 o2;
                o2.x = (silu_f(cs[2]) + silu_f(ct[2])) * INV_SQRT_2;
                o2.y = (silu_f(cs[3]) + silu_f(ct[3])) * INV_SQRT_2;
                *reinterpret_cast<float2*>(out + (size_t)er1 * 128 + col) = o2;
            }
        }
    }
}

// ===========================================================================
// Launch
// ===========================================================================
extern "C" void kernel_launch(void* const* d_in, const int* in_sizes, int n_in,
                              void* d_out, int out_size) {
    const float* m_st   = (const float*)d_in[0];
    const float* sbf    = (const float*)d_in[1];
    const void*  idxsw  = d_in[2];
    const float* W_down = (const float*)d_in[5];
    const float* W_bil  = (const float*)d_in[6];
    const float* W_st   = (const float*)d_in[7];
    const float* W_ts   = (const float*)d_in[8];
    const float* scale  = (const float*)d_in[9];
    float* out = (float*)d_out;

    const int E = in_sizes[0] / D_EDGE;
    const int ngroups16 = (E + 15) >> 4;

    cudaFuncSetAttribute(k_fused_a, cudaFuncAttributeMaxDynamicSharedMemorySize, KA_SMEM);
    k_fused_a<<<148, KA_WARPS * 32, KA_SMEM>>>(m_st, sbf, W_down, W_bil, scale, E);

    k_up_mma<<<(ngroups16 + KU_WARPS - 1) / KU_WARPS, KU_WARPS * 32>>>(idxsw, W_st, W_ts, out, E);
}